// round 16
// baseline (speedup 1.0000x reference)
#include <cuda_runtime.h>
#include <cstdint>

// Problem constants (fixed by dataset)
#define DDIM 256
#define CODES 1024
#define BM   64           // rows per CTA (2 CTAs/SM)
#define BN   64           // codes per chunk
#define NCHUNK 16
#define MARGIN 0.03f
#define TIE_ULPS 2
#define FILT_EPS 4e-3f

// dynamic smem layout (bytes) — total 77824 => 2 CTAs/SM
#define SM_CN     0          // 1024 f32 (4096)
#define SM_BIDX   4096       // 64 int (256)
#define SM_A_H    8192       // 64 rows x 272B (17408)
#define SM_A_L    25600      // 64 rows x 272B (17408)
#define SM_B      43008      // 2 mats x 64 x 272B (34816)
#define SM_TOTAL  77824
#define A_STRIDE  272        // 256 int8 + 16 pad (odd multiple of 16)
#define B_STRIDE  272
#define B_MAT     17408      // 64 * 272

__device__ float                      g_cnorm[1024];
__device__ __align__(256) int8_t      g_ch8[1024 * 256];
__device__ __align__(256) int8_t      g_cl8[1024 * 256];
__device__ int                        g_list[65536];
__device__ int                        g_cnt;

// ---------------------------------------------------------------------------
__device__ __forceinline__ uint32_t smem_to_u32(const void* p) {
    uint32_t a;
    asm("{ .reg .u64 t; cvta.to.shared.u64 t, %1; cvt.u32.u64 %0, t; }"
        : "=r"(a) : "l"(p));
    return a;
}
__device__ __forceinline__ void cp16(uint32_t dst, const void* src) {
    asm volatile("cp.async.cg.shared.global [%0], [%1], 16;"
                 :: "r"(dst), "l"(src));
}
#define CP_COMMIT() asm volatile("cp.async.commit_group;" ::: "memory")
#define CP_WAIT(n)  asm volatile("cp.async.wait_group %0;" :: "n"(n) : "memory")

__device__ __forceinline__ void ldsm4(uint32_t* r, uint32_t addr) {
    asm volatile("ldmatrix.sync.aligned.m8n8.x4.shared.b16 {%0,%1,%2,%3}, [%4];"
                 : "=r"(r[0]), "=r"(r[1]), "=r"(r[2]), "=r"(r[3]) : "r"(addr));
}
__device__ __forceinline__ void mma_s8(int* d, const uint32_t* a,
                                       const uint32_t* b) {
    asm volatile(
        "mma.sync.aligned.m16n8k32.row.col.s32.s8.s8.s32 "
        "{%0,%1,%2,%3}, {%4,%5,%6,%7}, {%8,%9}, {%0,%1,%2,%3};"
        : "+r"(d[0]), "+r"(d[1]), "+r"(d[2]), "+r"(d[3])
        : "r"(a[0]), "r"(a[1]), "r"(a[2]), "r"(a[3]), "r"(b[0]), "r"(b[1]));
}

// X = round(4096*x) in [-32768, 32639]; X = 256*h + l, h,l in [-128,127]
__device__ __forceinline__ void quant8(float v, int& h, int& l) {
    int X = __float2int_rn(v * 4096.0f);
    X = max(-32768, min(32639, X));
    h = (X + 128) >> 8;
    l = X - (h << 8);
}
__device__ __forceinline__ uint32_t pack4(int b0, int b1, int b2, int b3) {
    return  (uint32_t)(uint8_t)b0        | ((uint32_t)(uint8_t)b1 << 8)
         | ((uint32_t)(uint8_t)b2 << 16) | ((uint32_t)(uint8_t)b3 << 24);
}

// ---------------------------------------------------------------------------
// Prep: int8 hi/lo quantization of codes + ||c||^2 (fp64->fp32) + cnt reset.
__global__ void prep_codes(const float* __restrict__ codes) {
    __shared__ double partial[256];
    int c = blockIdx.x;
    int t = threadIdx.x;
    if (c == 0 && t == 0) g_cnt = 0;
    float v = codes[(size_t)c * DDIM + t];
    int h, l;
    quant8(v, h, l);
    g_ch8[(size_t)c * DDIM + t] = (int8_t)h;
    g_cl8[(size_t)c * DDIM + t] = (int8_t)l;
    partial[t] = (double)v * (double)v;
    __syncthreads();
    for (int s = 128; s; s >>= 1) {
        if (t < s) partial[t] += partial[t + s];
        __syncthreads();
    }
    if (t == 0) g_cnorm[c] = (float)partial[0];
}

// ---------------------------------------------------------------------------
// IMMA ranking kernel: BM=64, 256 threads / 8 warps (2m x 4n, warp 32x16),
// 2 CTAs/SM. dot*2^24 = 65536*hh + 256*(hl+lh) + ll (exact s32 GEMMs).
// ---------------------------------------------------------------------------
__global__ void __launch_bounds__(256, 2)
vq_mma(const float* __restrict__ x, const float* __restrict__ codes,
       float* __restrict__ out, long long out_size, int nrows)
{
    extern __shared__ char smem[];
    const uint32_t sb   = smem_to_u32(smem);
    const int tid  = threadIdx.x;
    const int wid  = tid >> 5;
    const int lane = tid & 31;
    const int wm   = wid & 1;          // m band: rows wm*32
    const int wn   = wid >> 1;         // n band: cols wn*16
    const int row_base = blockIdx.x * BM;

    float* cn_s   = (float*)(smem + SM_CN);
    int*   bidx_s = (int*)(smem + SM_BIDX);

    for (int i = tid; i < CODES; i += 256) cn_s[i] = g_cnorm[i];

    // --- quantize x rows into int8 hi/lo smem tiles ---
    for (int idx = tid; idx < BM * (DDIM / 8); idx += 256) {
        int r = idx >> 5;           // row 0..63
        int g = idx & 31;           // 8-elem group
        const float4* xp = (const float4*)(x + ((size_t)(row_base + r) * DDIM + g * 8));
        float4 v0 = xp[0], v1 = xp[1];
        int h0,l0,h1,l1,h2,l2,h3,l3,h4,l4,h5,l5,h6,l6,h7,l7;
        quant8(v0.x,h0,l0); quant8(v0.y,h1,l1); quant8(v0.z,h2,l2); quant8(v0.w,h3,l3);
        quant8(v1.x,h4,l4); quant8(v1.y,h5,l5); quant8(v1.z,h6,l6); quant8(v1.w,h7,l7);
        uint2 hp = make_uint2(pack4(h0,h1,h2,h3), pack4(h4,h5,h6,h7));
        uint2 lp = make_uint2(pack4(l0,l1,l2,l3), pack4(l4,l5,l6,l7));
        int off = r * A_STRIDE + g * 8;
        *(uint2*)(smem + SM_A_H + off) = hp;
        *(uint2*)(smem + SM_A_L + off) = lp;
    }
    __syncthreads();

    // per-lane top-2: 4 row slots (mt*2 + hi)
    float bv[4], b2[4];
    int   bi[4];
    #pragma unroll
    for (int i = 0; i < 4; i++) { bv[i] = 3.4e38f; b2[i] = 3.4e38f; bi[i] = 0; }

    for (int chunk = 0; chunk < NCHUNK; chunk++) {
        int acc_hh[2][2][4], acc_cr[2][2][4], acc_ll[2][2][4];
        #pragma unroll
        for (int m = 0; m < 2; m++)
            #pragma unroll
            for (int n = 0; n < 2; n++)
                #pragma unroll
                for (int q = 0; q < 4; q++) {
                    acc_hh[m][n][q] = 0; acc_cr[m][n][q] = 0; acc_ll[m][n][q] = 0;
                }

        // load B chunk: 2 mats x 64 codes x 256B = 2048 x 16B segs
        #pragma unroll
        for (int i = 0; i < 8; i++) {
            int linear = tid + i * 256;
            int mat = linear >> 10, rr = (linear >> 4) & 63, seg = linear & 15;
            uint32_t dst = sb + SM_B + mat * B_MAT + rr * B_STRIDE + seg * 16;
            const int8_t* src = (mat ? g_cl8 : g_ch8)
                + ((size_t)(chunk * BN + rr) * DDIM + seg * 16);
            cp16(dst, src);
        }
        CP_COMMIT();
        CP_WAIT(0);
        __syncthreads();

        #pragma unroll
        for (int k32 = 0; k32 < 8; k32++) {
            uint32_t ah[2][4], al[2][4];
            #pragma unroll
            for (int mt = 0; mt < 2; mt++) {
                uint32_t ar = sb + SM_A_H
                    + (wm * 32 + mt * 16 + (lane & 15)) * A_STRIDE
                    + k32 * 32 + (lane >> 4) * 16;
                ldsm4(ah[mt], ar);
                ldsm4(al[mt], ar + (SM_A_L - SM_A_H));
            }
            uint32_t bhf[4], blf[4];
            {
                uint32_t br = sb + SM_B
                    + (wn * 16 + (lane & 7) + ((lane >> 4) & 1) * 8) * B_STRIDE
                    + k32 * 32 + ((lane >> 3) & 1) * 16;
                ldsm4(bhf, br);
                ldsm4(blf, br + B_MAT);
            }
            #pragma unroll
            for (int n8 = 0; n8 < 2; n8++) {
                const uint32_t* bh = bhf + n8 * 2;
                const uint32_t* bl = blf + n8 * 2;
                #pragma unroll
                for (int mt = 0; mt < 2; mt++) {
                    mma_s8(acc_hh[mt][n8], ah[mt], bh);
                    mma_s8(acc_cr[mt][n8], ah[mt], bl);
                    mma_s8(acc_cr[mt][n8], al[mt], bh);
                    mma_s8(acc_ll[mt][n8], al[mt], bl);
                }
            }
        }
        __syncthreads();   // B consumed before next chunk overwrites

        // --- chunk epilogue: combine + scores + per-lane top-2 update ---
        const float INV = 5.9604644775390625e-8f;  // 1/2^24
        #pragma unroll
        for (int mt = 0; mt < 2; mt++) {
            #pragma unroll
            for (int n8 = 0; n8 < 2; n8++) {
                int col = chunk * BN + wn * 16 + n8 * 8 + (lane & 3) * 2;
                float d0 = ((float)acc_hh[mt][n8][0] * 65536.0f
                          + (float)acc_cr[mt][n8][0] * 256.0f
                          + (float)acc_ll[mt][n8][0]) * INV;
                float d1 = ((float)acc_hh[mt][n8][1] * 65536.0f
                          + (float)acc_cr[mt][n8][1] * 256.0f
                          + (float)acc_ll[mt][n8][1]) * INV;
                float d2 = ((float)acc_hh[mt][n8][2] * 65536.0f
                          + (float)acc_cr[mt][n8][2] * 256.0f
                          + (float)acc_ll[mt][n8][2]) * INV;
                float d3 = ((float)acc_hh[mt][n8][3] * 65536.0f
                          + (float)acc_cr[mt][n8][3] * 256.0f
                          + (float)acc_ll[mt][n8][3]) * INV;
                float s0 = cn_s[col]     - 2.0f * d0;
                float s1 = cn_s[col + 1] - 2.0f * d1;
                float s2 = cn_s[col]     - 2.0f * d2;
                float s3 = cn_s[col + 1] - 2.0f * d3;
                int sl0 = mt * 2, sl1 = mt * 2 + 1;
                if (s0 < bv[sl0]) { b2[sl0] = bv[sl0]; bv[sl0] = s0; bi[sl0] = col; }
                else b2[sl0] = fminf(b2[sl0], s0);
                if (s1 < bv[sl0]) { b2[sl0] = bv[sl0]; bv[sl0] = s1; bi[sl0] = col + 1; }
                else b2[sl0] = fminf(b2[sl0], s1);
                if (s2 < bv[sl1]) { b2[sl1] = bv[sl1]; bv[sl1] = s2; bi[sl1] = col; }
                else b2[sl1] = fminf(b2[sl1], s2);
                if (s3 < bv[sl1]) { b2[sl1] = bv[sl1]; bv[sl1] = s3; bi[sl1] = col + 1; }
                else b2[sl1] = fminf(b2[sl1], s3);
            }
        }
    }

    // --- cross-lane (quad) top-2 merge per row slot ---
    #pragma unroll
    for (int s = 0; s < 4; s++) {
        #pragma unroll
        for (int off = 1; off <= 2; off <<= 1) {
            float ov = __shfl_xor_sync(0xffffffffu, bv[s], off);
            float o2 = __shfl_xor_sync(0xffffffffu, b2[s], off);
            int   oi = __shfl_xor_sync(0xffffffffu, bi[s], off);
            float n2 = fminf(fminf(b2[s], o2), fmaxf(bv[s], ov));
            if (ov < bv[s] || (ov == bv[s] && oi < bi[s])) { bv[s] = ov; bi[s] = oi; }
            b2[s] = n2;
        }
    }
    __syncthreads();   // done with B buffer; reuse as merge scratch

    float* V1 = (float*)(smem + SM_B);            // [64][4]
    float* V2 = (float*)(smem + SM_B + 1024);
    int*   I1 = (int*)(smem + SM_B + 2048);
    if ((lane & 3) == 0) {
        #pragma unroll
        for (int s = 0; s < 4; s++) {
            int mt = s >> 1, hi = s & 1;
            int r = wm * 32 + mt * 16 + (lane >> 2) + hi * 8;
            V1[r * 4 + wn] = bv[s];
            V2[r * 4 + wn] = b2[s];
            I1[r * 4 + wn] = bi[s];
        }
    }
    __syncthreads();

    const long long NQ = (long long)nrows * DDIM;
    if (tid < BM) {
        float v1 = V1[tid * 4], v2 = V2[tid * 4];
        int   i1 = I1[tid * 4];
        #pragma unroll
        for (int j = 1; j < 4; j++) {
            float a1 = V1[tid * 4 + j], a2 = V2[tid * 4 + j];
            int   ai = I1[tid * 4 + j];
            float n2 = fminf(fminf(v2, a2), fmaxf(v1, a1));
            if (a1 < v1 || (a1 == v1 && ai < i1)) { v1 = a1; i1 = ai; }
            v2 = n2;
        }
        bidx_s[tid] = i1;
        long long row = row_base + tid;
        if (v2 - v1 < MARGIN) {
            int slot = atomicAdd(&g_cnt, 1);
            g_list[slot] = (int)row;
        }
        if (out_size >= NQ + nrows) out[NQ + row] = (float)i1;
        else if (out_size < NQ && row < out_size) out[row] = (float)i1;
    }
    __syncthreads();

    // --- gather quantized = codes[best] ---
    if (out_size >= NQ) {
        const float4* c4 = (const float4*)codes;
        float4* o4 = (float4*)out;
        for (int i = tid; i < BM * (DDIM / 4); i += 256) {
            int r = i >> 6;
            int q = i & 63;
            o4[(size_t)(row_base + r) * (DDIM / 4) + q] =
                c4[(size_t)bidx_s[r] * (DDIM / 4) + q];
        }
    }
}

// ---------------------------------------------------------------------------
// Refine kernel v6 (unchanged from R14/R15 pass): 1024 threads, one code per
// thread; fp32 prefilter + FILT_EPS, fp64 exact pass, tie-window select.
// ---------------------------------------------------------------------------
__global__ void __launch_bounds__(1024)
refine_kernel(const float* __restrict__ x, const float* __restrict__ codes,
              float* __restrict__ out, long long NQ, long long out_size,
              int nrows, int C)
{
    __shared__ __align__(16) float xr[DDIM];
    __shared__ double partial[256];
    __shared__ float  fv[1024];
    __shared__ int    fi[1024];
    __shared__ int    sel;
    __shared__ float  vm_s, filt_s;

    const int t = threadIdx.x;
    int cnt = g_cnt;
    if (cnt > 65536) cnt = 65536;

    for (int w = blockIdx.x; w < cnt; w += gridDim.x) {
        int row = g_list[w];
        if (t < DDIM) xr[t] = x[(size_t)row * DDIM + t];
        __syncthreads();

        if (t < 256) partial[t] = (double)xr[t] * (double)xr[t];
        __syncthreads();
        for (int s = 128; s; s >>= 1) {
            if (t < s) partial[t] += partial[t + s];
            __syncthreads();
        }
        float s1f = (float)partial[0];

        const int c = t;
        const float4* crow = (const float4*)(codes + (size_t)c * DDIM);
        const float4* xr4  = (const float4*)xr;
        float a0 = 0.f, a1 = 0.f, a2 = 0.f, a3 = 0.f;
        #pragma unroll 8
        for (int k4 = 0; k4 < DDIM / 4; k4++) {
            float4 cv = __ldg(&crow[k4]);
            float4 xv = xr4[k4];
            a0 = fmaf(cv.x, xv.x, a0);
            a1 = fmaf(cv.y, xv.y, a1);
            a2 = fmaf(cv.z, xv.z, a2);
            a3 = fmaf(cv.w, xv.w, a3);
        }
        float dot = (a0 + a1) + (a2 + a3);
        float dv  = (s1f - 2.0f * dot) + g_cnorm[c];

        fv[t] = dv;
        __syncthreads();
        for (int s = 512; s; s >>= 1) {
            if (t < s) fv[t] = fminf(fv[t], fv[t + s]);
            __syncthreads();
        }
        if (t == 0) filt_s = fv[0] + FILT_EPS;
        __syncthreads();
        float filt = filt_s;

        float ev = 3.4e38f;
        if (dv <= filt) {
            const float* cr = codes + (size_t)c * DDIM;
            double d0 = 0.0, d1 = 0.0, d2 = 0.0, d3 = 0.0;
            #pragma unroll 4
            for (int k = 0; k < DDIM; k += 4) {
                d0 = fma((double)xr[k],     (double)__ldg(&cr[k]),     d0);
                d1 = fma((double)xr[k + 1], (double)__ldg(&cr[k + 1]), d1);
                d2 = fma((double)xr[k + 2], (double)__ldg(&cr[k + 2]), d2);
                d3 = fma((double)xr[k + 3], (double)__ldg(&cr[k + 3]), d3);
            }
            double dd = (d0 + d1) + (d2 + d3);
            float dotf = (float)dd;
            float t1   = s1f - 2.0f * dotf;
            ev = t1 + g_cnorm[c];
        }

        fv[t] = ev;
        __syncthreads();
        for (int s = 512; s; s >>= 1) {
            if (t < s) fv[t] = fminf(fv[t], fv[t + s]);
            __syncthreads();
        }
        if (t == 0) vm_s = fv[0];
        __syncthreads();
        float vm = vm_s;
        float tie_hi = __int_as_float(__float_as_int(vm) + TIE_ULPS);

        fi[t] = (ev <= tie_hi) ? c : 0x7fffffff;
        __syncthreads();
        for (int s = 512; s; s >>= 1) {
            if (t < s) fi[t] = min(fi[t], fi[t + s]);
            __syncthreads();
        }
        if (t == 0) {
            sel = fi[0];
            if (out_size >= NQ + nrows) out[NQ + row] = (float)fi[0];
            else if (out_size < NQ && row < out_size) out[row] = (float)fi[0];
        }
        __syncthreads();

        if (out_size >= NQ && t < DDIM)
            out[(size_t)row * DDIM + t] = codes[(size_t)sel * DDIM + t];
        __syncthreads();
    }
}

// ---------------------------------------------------------------------------
extern "C" void kernel_launch(void* const* d_in, const int* in_sizes, int n_in,
                              void* d_out, int out_size)
{
    const float* x     = (const float*)d_in[0];
    const float* codes = (const float*)d_in[1];
    int nrows = in_sizes[0] / DDIM;   // 65536
    int C     = in_sizes[1] / DDIM;   // 1024

    cudaFuncSetAttribute(vq_mma, cudaFuncAttributeMaxDynamicSharedMemorySize,
                         SM_TOTAL);

    prep_codes<<<C, 256>>>(codes);

    vq_mma<<<nrows / BM, 256, SM_TOTAL>>>(x, codes, (float*)d_out,
                                          (long long)out_size, nrows);

    long long NQ = (long long)nrows * DDIM;
    refine_kernel<<<1024, 1024>>>(x, codes, (float*)d_out, NQ,
                                  (long long)out_size, nrows, C);
}

// round 17
// speedup vs baseline: 2.7116x; 2.7116x over previous
#include <cuda_runtime.h>
#include <cuda_bf16.h>
#include <cstdint>

// Problem constants (fixed by dataset)
#define DDIM 256
#define CODES 1024
#define BM   64           // rows per CTA (2 CTAs/SM)
#define BN   64           // codes per chunk
#define NCHUNK 16
#define MARGIN 2e-3f
#define TIE_ULPS 2
#define FILT_EPS 4e-3f

// dynamic smem layout (bytes) — total 112640 => 2 CTAs/SM
#define SM_CN     0          // 1024 f32 (4096)
#define SM_BIDX   4096       // 64 int (256)
#define SM_A_H    8192       // 64 rows x 528B (33792)
#define SM_A_L    41984      // 64 rows x 528B (33792)
#define SM_B      75776      // 2 stages x 2 mats x 64 x 144B (36864)
#define SM_TOTAL  112640
#define A_STRIDE  528        // bytes per A row (256 bf16 + pad)
#define B_STRIDE  144        // bytes per B row (64 bf16 + pad)
#define B_MAT     9216       // 64 * 144
#define B_STAGE   18432      // 2 matrices

__device__ float                          g_cnorm[1024];
__device__ __align__(256) __nv_bfloat16   g_ch[1024 * 256];
__device__ __align__(256) __nv_bfloat16   g_cl[1024 * 256];
__device__ int                            g_list[65536];
__device__ int                            g_cnt;

// ---------------------------------------------------------------------------
__device__ __forceinline__ uint32_t smem_to_u32(const void* p) {
    uint32_t a;
    asm("{ .reg .u64 t; cvta.to.shared.u64 t, %1; cvt.u32.u64 %0, t; }"
        : "=r"(a) : "l"(p));
    return a;
}
__device__ __forceinline__ void cp16(uint32_t dst, const void* src) {
    asm volatile("cp.async.cg.shared.global [%0], [%1], 16;"
                 :: "r"(dst), "l"(src));
}
#define CP_COMMIT() asm volatile("cp.async.commit_group;" ::: "memory")
#define CP_WAIT(n)  asm volatile("cp.async.wait_group %0;" :: "n"(n) : "memory")

__device__ __forceinline__ void ldsm4(uint32_t* r, uint32_t addr) {
    asm volatile("ldmatrix.sync.aligned.m8n8.x4.shared.b16 {%0,%1,%2,%3}, [%4];"
                 : "=r"(r[0]), "=r"(r[1]), "=r"(r[2]), "=r"(r[3]) : "r"(addr));
}
__device__ __forceinline__ void mma_bf16(float* d, const uint32_t* a,
                                         const uint32_t* b) {
    asm volatile(
        "mma.sync.aligned.m16n8k16.row.col.f32.bf16.bf16.f32 "
        "{%0,%1,%2,%3}, {%4,%5,%6,%7}, {%8,%9}, {%0,%1,%2,%3};"
        : "+f"(d[0]), "+f"(d[1]), "+f"(d[2]), "+f"(d[3])
        : "r"(a[0]), "r"(a[1]), "r"(a[2]), "r"(a[3]), "r"(b[0]), "r"(b[1]));
}

// ---------------------------------------------------------------------------
// Merged prep: bf16 hi/lo split + ||c||^2 (fp64 -> fp32) + g_cnt reset.
__global__ void prep_codes(const float* __restrict__ codes) {
    __shared__ double partial[256];
    int c = blockIdx.x;
    int t = threadIdx.x;
    if (c == 0 && t == 0) g_cnt = 0;
    float v = codes[(size_t)c * DDIM + t];
    __nv_bfloat16 h = __float2bfloat16_rn(v);
    float lo = v - __bfloat162float(h);
    g_ch[(size_t)c * DDIM + t] = h;
    g_cl[(size_t)c * DDIM + t] = __float2bfloat16_rn(lo);
    partial[t] = (double)v * (double)v;
    __syncthreads();
    for (int s = 128; s; s >>= 1) {
        if (t < s) partial[t] += partial[t + s];
        __syncthreads();
    }
    if (t == 0) g_cnorm[c] = (float)partial[0];
}

// ---------------------------------------------------------------------------
// HMMA ranking kernel: BM=64, 256 threads / 8 warps (2m x 4n, warp 32x16),
// 2 CTAs/SM, TWO-STAGE cp.async pipeline at BN=64 granularity.
// dot = xh.ch + xh.cl + xl.ch (bf16 in, fp32 acc)
// ---------------------------------------------------------------------------
__global__ void __launch_bounds__(256, 2)
vq_mma(const float* __restrict__ x, const float* __restrict__ codes,
       float* __restrict__ out, long long out_size, int nrows)
{
    extern __shared__ char smem[];
    const uint32_t sb   = smem_to_u32(smem);
    const int tid  = threadIdx.x;
    const int wid  = tid >> 5;
    const int lane = tid & 31;
    const int wm   = wid & 1;          // m band: rows wm*32
    const int wn   = wid >> 1;         // n band: cols wn*16
    const int row_base = blockIdx.x * BM;

    float* cn_s   = (float*)(smem + SM_CN);
    int*   bidx_s = (int*)(smem + SM_BIDX);

    for (int i = tid; i < CODES; i += 256) cn_s[i] = g_cnorm[i];

    // --- convert x rows to bf16 hi/lo in smem ---
    const float4* x4 = (const float4*)x + (size_t)row_base * (DDIM / 4);
    for (int idx = tid; idx < BM * (DDIM / 4); idx += 256) {
        float4 v = x4[idx];
        int r  = idx >> 6;
        int kq = idx & 63;
        __nv_bfloat16 h0 = __float2bfloat16_rn(v.x);
        __nv_bfloat16 h1 = __float2bfloat16_rn(v.y);
        __nv_bfloat16 h2 = __float2bfloat16_rn(v.z);
        __nv_bfloat16 h3 = __float2bfloat16_rn(v.w);
        __nv_bfloat16 l0 = __float2bfloat16_rn(v.x - __bfloat162float(h0));
        __nv_bfloat16 l1 = __float2bfloat16_rn(v.y - __bfloat162float(h1));
        __nv_bfloat16 l2 = __float2bfloat16_rn(v.z - __bfloat162float(h2));
        __nv_bfloat16 l3 = __float2bfloat16_rn(v.w - __bfloat162float(h3));
        uint32_t h01 = ((uint32_t)__bfloat16_as_ushort(h1) << 16) | __bfloat16_as_ushort(h0);
        uint32_t h23 = ((uint32_t)__bfloat16_as_ushort(h3) << 16) | __bfloat16_as_ushort(h2);
        uint32_t l01 = ((uint32_t)__bfloat16_as_ushort(l1) << 16) | __bfloat16_as_ushort(l0);
        uint32_t l23 = ((uint32_t)__bfloat16_as_ushort(l3) << 16) | __bfloat16_as_ushort(l2);
        int off = r * A_STRIDE + kq * 8;
        *(uint32_t*)(smem + SM_A_H + off)     = h01;
        *(uint32_t*)(smem + SM_A_H + off + 4) = h23;
        *(uint32_t*)(smem + SM_A_L + off)     = l01;
        *(uint32_t*)(smem + SM_A_L + off + 4) = l23;
    }

    // per-lane top-2: 4 row slots (mt*2 + hi)
    float bv[4], b2[4];
    int   bi[4];
    #pragma unroll
    for (int i = 0; i < 4; i++) { bv[i] = 3.4e38f; b2[i] = 3.4e38f; bi[i] = 0; }

    // B load for pipeline step (chunk,ks) into stage buf
    #define LOADB(CHUNK, KS, BUF) do {                                         \
        _Pragma("unroll")                                                      \
        for (int i_ = 0; i_ < 4; i_++) {                                       \
            int linear = tid + i_ * 256;                                       \
            int mat = linear >> 9, rr = (linear >> 3) & 63, seg = linear & 7;  \
            uint32_t dst = sb + SM_B + (BUF) * B_STAGE + mat * B_MAT           \
                         + rr * B_STRIDE + seg * 16;                           \
            const __nv_bfloat16* src = (mat ? g_cl : g_ch)                     \
                + ((size_t)((CHUNK) * BN + rr) * DDIM + (KS) * 64 + seg * 8);  \
            cp16(dst, src);                                                    \
        }                                                                      \
    } while (0)

    const int TSTEPS = NCHUNK * 4;   // 64
    LOADB(0, 0, 0);
    CP_COMMIT();

    float acc[2][2][4];

    for (int t = 0; t < TSTEPS; t++) {
        const int chunk = t >> 2, ks = t & 3, buf = t & 1;
        if (ks == 0) {
            #pragma unroll
            for (int m = 0; m < 2; m++)
                #pragma unroll
                for (int n = 0; n < 2; n++)
                    #pragma unroll
                    for (int q = 0; q < 4; q++) acc[m][n][q] = 0.0f;
        }
        __syncthreads();   // previous step's compute done -> safe to overwrite !buf
        if (t + 1 < TSTEPS) {
            int nt = t + 1;
            LOADB(nt >> 2, nt & 3, nt & 1);
            CP_COMMIT();
            CP_WAIT(1);    // load for current buf (issued at t-1) complete
        } else {
            CP_WAIT(0);
        }
        __syncthreads();

        const uint32_t bbase = sb + SM_B + buf * B_STAGE;
        #pragma unroll
        for (int k16 = 0; k16 < 4; k16++) {
            int kel = k16 * 16;
            uint32_t ah[2][4], al[2][4];
            #pragma unroll
            for (int mt = 0; mt < 2; mt++) {
                uint32_t ar = sb + SM_A_H
                    + (wm * 32 + mt * 16 + (lane & 15)) * A_STRIDE
                    + (ks * 64 + kel + (lane >> 4) * 8) * 2;
                ldsm4(ah[mt], ar);
                ldsm4(al[mt], ar + (SM_A_L - SM_A_H));
            }
            uint32_t bh[4], bl[4];
            {
                uint32_t br = bbase
                    + (wn * 16 + (lane & 7) + (lane >> 4) * 8) * B_STRIDE
                    + (kel + ((lane >> 3) & 1) * 8) * 2;
                ldsm4(bh, br);
                ldsm4(bl, br + B_MAT);
            }
            #pragma unroll
            for (int n8 = 0; n8 < 2; n8++) {
                const uint32_t* bhp = bh + n8 * 2;
                const uint32_t* blp = bl + n8 * 2;
                #pragma unroll
                for (int mt = 0; mt < 2; mt++) {
                    mma_bf16(acc[mt][n8], ah[mt], bhp);
                    mma_bf16(acc[mt][n8], ah[mt], blp);
                    mma_bf16(acc[mt][n8], al[mt], bhp);
                }
            }
        }

        if (ks == 3) {
            // --- chunk epilogue: scores + per-lane top-2 update ---
            #pragma unroll
            for (int mt = 0; mt < 2; mt++) {
                #pragma unroll
                for (int n8 = 0; n8 < 2; n8++) {
                    int col = chunk * BN + wn * 16 + n8 * 8 + (lane & 3) * 2;
                    float s0 = cn_s[col]     - 2.0f * acc[mt][n8][0];
                    float s1 = cn_s[col + 1] - 2.0f * acc[mt][n8][1];
                    float s2 = cn_s[col]     - 2.0f * acc[mt][n8][2];
                    float s3 = cn_s[col + 1] - 2.0f * acc[mt][n8][3];
                    int sl0 = mt * 2, sl1 = mt * 2 + 1;
                    if (s0 < bv[sl0]) { b2[sl0] = bv[sl0]; bv[sl0] = s0; bi[sl0] = col; }
                    else b2[sl0] = fminf(b2[sl0], s0);
                    if (s1 < bv[sl0]) { b2[sl0] = bv[sl0]; bv[sl0] = s1; bi[sl0] = col + 1; }
                    else b2[sl0] = fminf(b2[sl0], s1);
                    if (s2 < bv[sl1]) { b2[sl1] = bv[sl1]; bv[sl1] = s2; bi[sl1] = col; }
                    else b2[sl1] = fminf(b2[sl1], s2);
                    if (s3 < bv[sl1]) { b2[sl1] = bv[sl1]; bv[sl1] = s3; bi[sl1] = col + 1; }
                    else b2[sl1] = fminf(b2[sl1], s3);
                }
            }
        }
    }
    #undef LOADB

    // --- cross-lane (quad) top-2 merge per row slot ---
    #pragma unroll
    for (int s = 0; s < 4; s++) {
        #pragma unroll
        for (int off = 1; off <= 2; off <<= 1) {
            float ov = __shfl_xor_sync(0xffffffffu, bv[s], off);
            float o2 = __shfl_xor_sync(0xffffffffu, b2[s], off);
            int   oi = __shfl_xor_sync(0xffffffffu, bi[s], off);
            float n2 = fminf(fminf(b2[s], o2), fmaxf(bv[s], ov));
            if (ov < bv[s] || (ov == bv[s] && oi < bi[s])) { bv[s] = ov; bi[s] = oi; }
            b2[s] = n2;
        }
    }
    __syncthreads();   // done with B buffer; reuse as merge scratch

    float* V1 = (float*)(smem + SM_B);            // [64][4]
    float* V2 = (float*)(smem + SM_B + 1024);
    int*   I1 = (int*)(smem + SM_B + 2048);
    if ((lane & 3) == 0) {
        #pragma unroll
        for (int s = 0; s < 4; s++) {
            int mt = s >> 1, hi = s & 1;
            int r = wm * 32 + mt * 16 + (lane >> 2) + hi * 8;
            V1[r * 4 + wn] = bv[s];
            V2[r * 4 + wn] = b2[s];
            I1[r * 4 + wn] = bi[s];
        }
    }
    __syncthreads();

    const long long NQ = (long long)nrows * DDIM;
    if (tid < BM) {
        float v1 = V1[tid * 4], v2 = V2[tid * 4];
        int   i1 = I1[tid * 4];
        #pragma unroll
        for (int j = 1; j < 4; j++) {
            float a1 = V1[tid * 4 + j], a2 = V2[tid * 4 + j];
            int   ai = I1[tid * 4 + j];
            float n2 = fminf(fminf(v2, a2), fmaxf(v1, a1));
            if (a1 < v1 || (a1 == v1 && ai < i1)) { v1 = a1; i1 = ai; }
            v2 = n2;
        }
        bidx_s[tid] = i1;
        long long row = row_base + tid;
        if (v2 - v1 < MARGIN) {
            int slot = atomicAdd(&g_cnt, 1);
            g_list[slot] = (int)row;
        }
        if (out_size >= NQ + nrows) out[NQ + row] = (float)i1;
        else if (out_size < NQ && row < out_size) out[row] = (float)i1;
    }
    __syncthreads();

    // --- gather quantized = codes[best] ---
    if (out_size >= NQ) {
        const float4* c4 = (const float4*)codes;
        float4* o4 = (float4*)out;
        for (int i = tid; i < BM * (DDIM / 4); i += 256) {
            int r = i >> 6;
            int q = i & 63;
            o4[(size_t)(row_base + r) * (DDIM / 4) + q] =
                c4[(size_t)bidx_s[r] * (DDIM / 4) + q];
        }
    }
}

// ---------------------------------------------------------------------------
// Refine kernel v6 (unchanged from R14/R15 pass): 1024 threads, one code per
// thread; fp32 prefilter + FILT_EPS, fp64 exact pass, tie-window select.
// ---------------------------------------------------------------------------
__global__ void __launch_bounds__(1024)
refine_kernel(const float* __restrict__ x, const float* __restrict__ codes,
              float* __restrict__ out, long long NQ, long long out_size,
              int nrows, int C)
{
    __shared__ __align__(16) float xr[DDIM];
    __shared__ double partial[256];
    __shared__ float  fv[1024];
    __shared__ int    fi[1024];
    __shared__ int    sel;
    __shared__ float  vm_s, filt_s;

    const int t = threadIdx.x;
    int cnt = g_cnt;
    if (cnt > 65536) cnt = 65536;

    for (int w = blockIdx.x; w < cnt; w += gridDim.x) {
        int row = g_list[w];
        if (t < DDIM) xr[t] = x[(size_t)row * DDIM + t];
        __syncthreads();

        if (t < 256) partial[t] = (double)xr[t] * (double)xr[t];
        __syncthreads();
        for (int s = 128; s; s >>= 1) {
            if (t < s) partial[t] += partial[t + s];
            __syncthreads();
        }
        float s1f = (float)partial[0];

        const int c = t;
        const float4* crow = (const float4*)(codes + (size_t)c * DDIM);
        const float4* xr4  = (const float4*)xr;
        float a0 = 0.f, a1 = 0.f, a2 = 0.f, a3 = 0.f;
        #pragma unroll 8
        for (int k4 = 0; k4 < DDIM / 4; k4++) {
            float4 cv = __ldg(&crow[k4]);
            float4 xv = xr4[k4];
            a0 = fmaf(cv.x, xv.x, a0);
            a1 = fmaf(cv.y, xv.y, a1);
            a2 = fmaf(cv.z, xv.z, a2);
            a3 = fmaf(cv.w, xv.w, a3);
        }
        float dot = (a0 + a1) + (a2 + a3);
        float dv  = (s1f - 2.0f * dot) + g_cnorm[c];

        fv[t] = dv;
        __syncthreads();
        for (int s = 512; s; s >>= 1) {
            if (t < s) fv[t] = fminf(fv[t], fv[t + s]);
            __syncthreads();
        }
        if (t == 0) filt_s = fv[0] + FILT_EPS;
        __syncthreads();
        float filt = filt_s;

        float ev = 3.4e38f;
        if (dv <= filt) {
            const float* cr = codes + (size_t)c * DDIM;
            double d0 = 0.0, d1 = 0.0, d2 = 0.0, d3 = 0.0;
            #pragma unroll 4
            for (int k = 0; k < DDIM; k += 4) {
                d0 = fma((double)xr[k],     (double)__ldg(&cr[k]),     d0);
                d1 = fma((double)xr[k + 1], (double)__ldg(&cr[k + 1]), d1);
                d2 = fma((double)xr[k + 2], (double)__ldg(&cr[k + 2]), d2);
                d3 = fma((double)xr[k + 3], (double)__ldg(&cr[k + 3]), d3);
            }
            double dd = (d0 + d1) + (d2 + d3);
            float dotf = (float)dd;
            float t1   = s1f - 2.0f * dotf;
            ev = t1 + g_cnorm[c];
        }

        fv[t] = ev;
        __syncthreads();
        for (int s = 512; s; s >>= 1) {
            if (t < s) fv[t] = fminf(fv[t], fv[t + s]);
            __syncthreads();
        }
        if (t == 0) vm_s = fv[0];
        __syncthreads();
        float vm = vm_s;
        float tie_hi = __int_as_float(__float_as_int(vm) + TIE_ULPS);

        fi[t] = (ev <= tie_hi) ? c : 0x7fffffff;
        __syncthreads();
        for (int s = 512; s; s >>= 1) {
            if (t < s) fi[t] = min(fi[t], fi[t + s]);
            __syncthreads();
        }
        if (t == 0) {
            sel = fi[0];
            if (out_size >= NQ + nrows) out[NQ + row] = (float)fi[0];
            else if (out_size < NQ && row < out_size) out[row] = (float)fi[0];
        }
        __syncthreads();

        if (out_size >= NQ && t < DDIM)
            out[(size_t)row * DDIM + t] = codes[(size_t)sel * DDIM + t];
        __syncthreads();
    }
}

// ---------------------------------------------------------------------------
extern "C" void kernel_launch(void* const* d_in, const int* in_sizes, int n_in,
                              void* d_out, int out_size)
{
    const float* x     = (const float*)d_in[0];
    const float* codes = (const float*)d_in[1];
    int nrows = in_sizes[0] / DDIM;   // 65536
    int C     = in_sizes[1] / DDIM;   // 1024

    cudaFuncSetAttribute(vq_mma, cudaFuncAttributeMaxDynamicSharedMemorySize,
                         SM_TOTAL);

    prep_codes<<<C, 256>>>(codes);

    vq_mma<<<nrows / BM, 256, SM_TOTAL>>>(x, codes, (float*)d_out,
                                          (long long)out_size, nrows);

    long long NQ = (long long)nrows * DDIM;
    refine_kernel<<<1024, 1024>>>(x, codes, (float*)d_out, NQ,
                                  (long long)out_size, nrows, C);
}